// round 1
// baseline (speedup 1.0000x reference)
#include <cuda_runtime.h>

#define NN     50000
#define F0     128
#define HC     256
#define NHEADS 4
#define CH     64
#define EMAX   900000
#define SLOPE  0.2f

// ---------------- scratch (static device globals; no allocs allowed) -------
__device__ float g_h[(long long)NN * HC];   // post-GEMM features, current layer
__device__ float g_x[(long long)NN * HC];   // layer output / next layer input
__device__ float g_as[NN * NHEADS];         // a_src per node/head
__device__ float g_ad[NN * NHEADS];         // a_dst per node/head
__device__ int   g_rowptr[NN + 1];          // CSR by destination
__device__ int   g_off[NN];                 // counts / running offsets
__device__ int   g_col[EMAX];               // src node per CSR slot

// ---------------- CSR build ------------------------------------------------
__global__ void zero_off_kernel() {
    int i = blockIdx.x * blockDim.x + threadIdx.x;
    if (i < NN) g_off[i] = 0;
}

__global__ void count_kernel(const int* __restrict__ dst, int E) {
    int e = blockIdx.x * blockDim.x + threadIdx.x;
    if (e < E) atomicAdd(&g_off[dst[e]], 1);
}

// single-block exclusive scan over 50000 counts -> rowptr, and seed offsets
__global__ void scan_kernel() {
    __shared__ int part[1024];
    int t = threadIdx.x;
    const int CHK = (NN + 1023) / 1024;     // 49
    int lo = t * CHK;
    int hi = lo + CHK; if (hi > NN) hi = NN;
    if (lo > NN) lo = NN;
    int s = 0;
    for (int i = lo; i < hi; i++) s += g_off[i];
    part[t] = s;
    __syncthreads();
    for (int d = 1; d < 1024; d <<= 1) {
        int v = (t >= d) ? part[t - d] : 0;
        __syncthreads();
        part[t] += v;
        __syncthreads();
    }
    int pre = (t == 0) ? 0 : part[t - 1];
    for (int i = lo; i < hi; i++) {
        int c = g_off[i];
        g_rowptr[i] = pre;
        g_off[i]    = pre;   // running scatter offset
        pre += c;
    }
    if (t == 1023) g_rowptr[NN] = part[1023];
}

__global__ void scatter_kernel(const int* __restrict__ src,
                               const int* __restrict__ dst, int E) {
    int e = blockIdx.x * blockDim.x + threadIdx.x;
    if (e < E) {
        int p = atomicAdd(&g_off[dst[e]], 1);
        g_col[p] = src[e];
    }
}

// ---------------- GEMM: h = A[M,K] @ W[K,256] ------------------------------
// 64x64 tile, BK=16, 256 threads, 4x4 microtile, float4 smem reads.
__global__ void gemm_kernel(const float* __restrict__ A,
                            const float* __restrict__ B,
                            float* __restrict__ Cmat, int M, int K) {
    __shared__ float As[16][68];   // transposed A tile, +4 pad (float4-aligned rows)
    __shared__ float Bs[16][64];
    int tid = threadIdx.x;
    int tx = tid & 15, ty = tid >> 4;
    int m0 = blockIdx.y * 64;
    int n0 = blockIdx.x * 64;
    int arow = tid >> 2, ac4 = (tid & 3) * 4;
    int brow = tid >> 4, bc4 = (tid & 15) * 4;

    float c[4][4] = {};
    for (int k0 = 0; k0 < K; k0 += 16) {
        float4 av = make_float4(0.f, 0.f, 0.f, 0.f);
        if (m0 + arow < M)
            av = *(const float4*)&A[(long long)(m0 + arow) * K + k0 + ac4];
        As[ac4 + 0][arow] = av.x;
        As[ac4 + 1][arow] = av.y;
        As[ac4 + 2][arow] = av.z;
        As[ac4 + 3][arow] = av.w;
        float4 bv = *(const float4*)&B[(long long)(k0 + brow) * HC + n0 + bc4];
        *(float4*)&Bs[brow][bc4] = bv;
        __syncthreads();
#pragma unroll
        for (int k = 0; k < 16; k++) {
            float4 a = *(const float4*)&As[k][ty * 4];
            float4 b = *(const float4*)&Bs[k][tx * 4];
            c[0][0] += a.x * b.x; c[0][1] += a.x * b.y; c[0][2] += a.x * b.z; c[0][3] += a.x * b.w;
            c[1][0] += a.y * b.x; c[1][1] += a.y * b.y; c[1][2] += a.y * b.z; c[1][3] += a.y * b.w;
            c[2][0] += a.z * b.x; c[2][1] += a.z * b.y; c[2][2] += a.z * b.z; c[2][3] += a.z * b.w;
            c[3][0] += a.w * b.x; c[3][1] += a.w * b.y; c[3][2] += a.w * b.z; c[3][3] += a.w * b.w;
        }
        __syncthreads();
    }
#pragma unroll
    for (int i = 0; i < 4; i++) {
        int row = m0 + ty * 4 + i;
        if (row < M)
            *(float4*)&Cmat[(long long)row * HC + n0 + tx * 4] =
                make_float4(c[i][0], c[i][1], c[i][2], c[i][3]);
    }
}

// ---------------- attention logits: a_src/a_dst per (node, head) -----------
__global__ void attn_kernel(const float* __restrict__ att_src,
                            const float* __restrict__ att_dst) {
    int gw = (blockIdx.x * blockDim.x + threadIdx.x) >> 5;
    int lane = threadIdx.x & 31;
    if (gw >= NN * NHEADS) return;
    int n = gw >> 2, hd = gw & 3;
    const float* hp = &g_h[(long long)n * HC + hd * CH];
    float h0 = hp[lane], h1 = hp[lane + 32];
    float s1 = h0 * att_src[hd * CH + lane] + h1 * att_src[hd * CH + lane + 32];
    float s2 = h0 * att_dst[hd * CH + lane] + h1 * att_dst[hd * CH + lane + 32];
#pragma unroll
    for (int d = 16; d; d >>= 1) {
        s1 += __shfl_xor_sync(0xffffffffu, s1, d);
        s2 += __shfl_xor_sync(0xffffffffu, s2, d);
    }
    if (lane == 0) {
        g_as[n * NHEADS + hd] = s1;
        g_ad[n * NHEADS + hd] = s2;
    }
}

// ---------------- aggregation: warp per destination node -------------------
// pass1: warp-parallel max of leaky(a_src[s]+a_dst[n]) per head
// pass2: sequential over edges; ex = exp(e - m); acc += ex * h[src]; den += ex
// epilogue: relu(acc/den + bias)
__global__ void agg_kernel(const float* __restrict__ bias, float* __restrict__ out) {
    int warp = (blockIdx.x * blockDim.x + threadIdx.x) >> 5;
    int lane = threadIdx.x & 31;
    if (warp >= NN) return;
    int n = warp;
    int beg = g_rowptr[n], end = g_rowptr[n + 1];
    float4 ad4 = *(const float4*)&g_ad[n * 4];

    float m0 = -1e30f, m1 = -1e30f, m2 = -1e30f, m3 = -1e30f;
    for (int e = beg + lane; e < end; e += 32) {
        int s = g_col[e];
        float4 a4 = *(const float4*)&g_as[s * 4];
        float v;
        v = a4.x + ad4.x; v = v > 0.f ? v : SLOPE * v; m0 = fmaxf(m0, v);
        v = a4.y + ad4.y; v = v > 0.f ? v : SLOPE * v; m1 = fmaxf(m1, v);
        v = a4.z + ad4.z; v = v > 0.f ? v : SLOPE * v; m2 = fmaxf(m2, v);
        v = a4.w + ad4.w; v = v > 0.f ? v : SLOPE * v; m3 = fmaxf(m3, v);
    }
#pragma unroll
    for (int d = 16; d; d >>= 1) {
        m0 = fmaxf(m0, __shfl_xor_sync(0xffffffffu, m0, d));
        m1 = fmaxf(m1, __shfl_xor_sync(0xffffffffu, m1, d));
        m2 = fmaxf(m2, __shfl_xor_sync(0xffffffffu, m2, d));
        m3 = fmaxf(m3, __shfl_xor_sync(0xffffffffu, m3, d));
    }
    int hd = lane >> 3;
    float mh  = (hd == 0) ? m0 : (hd == 1) ? m1 : (hd == 2) ? m2 : m3;
    float adh = (hd == 0) ? ad4.x : (hd == 1) ? ad4.y : (hd == 2) ? ad4.z : ad4.w;

    int cbase = lane * 8;
    float acc[8] = {0.f, 0.f, 0.f, 0.f, 0.f, 0.f, 0.f, 0.f};
    float den = 0.f;
    for (int e = beg; e < end; e++) {
        int s = g_col[e];                        // warp-uniform broadcast
        float av = g_as[s * 4 + hd];
        float ee = av + adh;
        ee = ee > 0.f ? ee : SLOPE * ee;
        float ex = __expf(ee - mh);
        den += ex;
        const float4* hp = (const float4*)&g_h[(long long)s * HC + cbase];
        float4 h0 = hp[0], h1 = hp[1];           // coalesced 1KB per warp
        acc[0] += ex * h0.x; acc[1] += ex * h0.y; acc[2] += ex * h0.z; acc[3] += ex * h0.w;
        acc[4] += ex * h1.x; acc[5] += ex * h1.y; acc[6] += ex * h1.z; acc[7] += ex * h1.w;
    }
    float inv = 1.f / (den + 1e-16f);
    float4 b0 = *(const float4*)&bias[cbase];
    float4 b1 = *(const float4*)&bias[cbase + 4];
    float4 o0, o1;
    o0.x = fmaxf(acc[0] * inv + b0.x, 0.f);
    o0.y = fmaxf(acc[1] * inv + b0.y, 0.f);
    o0.z = fmaxf(acc[2] * inv + b0.z, 0.f);
    o0.w = fmaxf(acc[3] * inv + b0.w, 0.f);
    o1.x = fmaxf(acc[4] * inv + b1.x, 0.f);
    o1.y = fmaxf(acc[5] * inv + b1.y, 0.f);
    o1.z = fmaxf(acc[6] * inv + b1.z, 0.f);
    o1.w = fmaxf(acc[7] * inv + b1.w, 0.f);
    *(float4*)&out[(long long)n * HC + cbase]     = o0;
    *(float4*)&out[(long long)n * HC + cbase + 4] = o1;
}

// ---------------- launcher -------------------------------------------------
extern "C" void kernel_launch(void* const* d_in, const int* in_sizes, int n_in,
                              void* d_out, int out_size) {
    const float* x  = (const float*)d_in[0];
    const int*   ei = (const int*)d_in[1];
    int E = in_sizes[1] / 2;
    const int* src = ei;
    const int* dst = ei + E;

    const float* W[3]  = {(const float*)d_in[2], (const float*)d_in[6],  (const float*)d_in[10]};
    const float* AS[3] = {(const float*)d_in[3], (const float*)d_in[7],  (const float*)d_in[11]};
    const float* AD[3] = {(const float*)d_in[4], (const float*)d_in[8],  (const float*)d_in[12]};
    const float* BI[3] = {(const float*)d_in[5], (const float*)d_in[9],  (const float*)d_in[13]};
    float* out = (float*)d_out;

    float* gx = nullptr;
    float* gh = nullptr;
    cudaGetSymbolAddress((void**)&gx, g_x);
    cudaGetSymbolAddress((void**)&gh, g_h);

    // CSR build (edge_index is identical for all layers)
    zero_off_kernel<<<(NN + 255) / 256, 256>>>();
    count_kernel<<<(E + 255) / 256, 256>>>(dst, E);
    scan_kernel<<<1, 1024>>>();
    scatter_kernel<<<(E + 255) / 256, 256>>>(src, dst, E);

    dim3 ggrid(HC / 64, (NN + 63) / 64);
    int attn_blocks = (NN * NHEADS * 32 + 255) / 256;
    int agg_blocks  = (NN + 7) / 8;

    // layer 0 (K = 128)
    gemm_kernel<<<ggrid, 256>>>(x, W[0], gh, NN, F0);
    attn_kernel<<<attn_blocks, 256>>>(AS[0], AD[0]);
    agg_kernel<<<agg_blocks, 256>>>(BI[0], gx);

    // layer 1 (K = 256)
    gemm_kernel<<<ggrid, 256>>>(gx, W[1], gh, NN, HC);
    attn_kernel<<<attn_blocks, 256>>>(AS[1], AD[1]);
    agg_kernel<<<agg_blocks, 256>>>(BI[1], gx);

    // layer 2 (K = 256), write final output
    gemm_kernel<<<ggrid, 256>>>(gx, W[2], gh, NN, HC);
    attn_kernel<<<attn_blocks, 256>>>(AS[2], AD[2]);
    agg_kernel<<<agg_blocks, 256>>>(BI[2], out);
}

// round 4
// speedup vs baseline: 1.1869x; 1.1869x over previous
#include <cuda_runtime.h>
#include <mma.h>

using namespace nvcuda;

#define NN     50000
#define F0     128
#define HC     256
#define NHEADS 4
#define CH     64
#define EMAX   900000
#define SLOPE  0.2f

// ---------------- scratch (static device globals; no allocs allowed) -------
__device__ float g_h[(long long)NN * HC];   // post-GEMM features, current layer
__device__ float g_x[(long long)NN * HC];   // layer output / next layer input
__device__ float g_as[NN * NHEADS];         // a_src per node/head
__device__ float g_ad[NN * NHEADS];         // a_dst per node/head
__device__ int   g_rowptr[NN + 1];          // CSR by destination
__device__ int   g_off[NN];                 // counts / running offsets
__device__ int   g_col[EMAX];               // src node per CSR slot

// ---------------- CSR build ------------------------------------------------
__global__ void zero_off_kernel() {
    int i = blockIdx.x * blockDim.x + threadIdx.x;
    if (i < NN) g_off[i] = 0;
}

__global__ void count_kernel(const int* __restrict__ dst, int E) {
    int e = blockIdx.x * blockDim.x + threadIdx.x;
    if (e < E) atomicAdd(&g_off[dst[e]], 1);
}

__global__ void scan_kernel() {
    __shared__ int part[1024];
    int t = threadIdx.x;
    const int CHK = (NN + 1023) / 1024;
    int lo = t * CHK;
    int hi = lo + CHK; if (hi > NN) hi = NN;
    if (lo > NN) lo = NN;
    int s = 0;
    for (int i = lo; i < hi; i++) s += g_off[i];
    part[t] = s;
    __syncthreads();
    for (int d = 1; d < 1024; d <<= 1) {
        int v = (t >= d) ? part[t - d] : 0;
        __syncthreads();
        part[t] += v;
        __syncthreads();
    }
    int pre = (t == 0) ? 0 : part[t - 1];
    for (int i = lo; i < hi; i++) {
        int c = g_off[i];
        g_rowptr[i] = pre;
        g_off[i]    = pre;
        pre += c;
    }
    if (t == 1023) g_rowptr[NN] = part[1023];
}

__global__ void scatter_kernel(const int* __restrict__ src,
                               const int* __restrict__ dst, int E) {
    int e = blockIdx.x * blockDim.x + threadIdx.x;
    if (e < E) {
        int p = atomicAdd(&g_off[dst[e]], 1);
        g_col[p] = src[e];
    }
}

// ---------------- TF32 tensor-core GEMM via wmma: C = A[M,K] @ B[K,256] ----
// BM=128, BN=64, BK=32. 256 threads = 8 warps laid out 4(m) x 2(n),
// warp tile 32x32 = 2x2 wmma fragments of m16n16k8 (tf32, fp32 accumulate).
// M (=NN=50000) is a multiple of 16, so each 16x16 output fragment is either
// fully in-bounds or fully out: per-fragment row guard suffices.

#define BM 128
#define BN 64
#define BK 32
#define APAD 4
#define BPAD 4

__global__ __launch_bounds__(256)
void gemm_tf32_kernel(const float* __restrict__ A,
                      const float* __restrict__ B,
                      float* __restrict__ Cmat, int M, int K) {
    __shared__ float As[BM][BK + APAD];   // [m][k] row-major (tf32 bits in float)
    __shared__ float Bs[BK][BN + BPAD];   // [k][n] row-major

    int tid  = threadIdx.x;
    int warp = tid >> 5;
    int wm   = warp >> 1;        // 0..3 -> m offset wm*32
    int wn   = warp & 1;         // 0..1 -> n offset wn*32

    int m0 = blockIdx.y * BM;
    int n0 = blockIdx.x * BN;

    // A load mapping: row = tid>>1 (0..127), kbase = (tid&1)*16 (4 x float4)
    int ar = tid >> 1;
    int ak = (tid & 1) * 16;
    // B load mapping: row = tid>>3 (0..31), cbase = (tid&7)*8 (2 x float4)
    int br = tid >> 3;
    int bc = (tid & 7) * 8;

    wmma::fragment<wmma::accumulator, 16, 16, 8, float> c[2][2];
#pragma unroll
    for (int i = 0; i < 2; i++)
#pragma unroll
        for (int j = 0; j < 2; j++)
            wmma::fill_fragment(c[i][j], 0.0f);

    for (int k0 = 0; k0 < K; k0 += BK) {
        // load A tile (128 x 32) -> As[m][k], converted to tf32
        bool arow_ok = (m0 + ar) < M;
        const float* ap = A + (long long)(m0 + ar) * K + k0 + ak;
#pragma unroll
        for (int i = 0; i < 4; i++) {
            float4 v = arow_ok ? *(const float4*)(ap + i * 4)
                               : make_float4(0.f, 0.f, 0.f, 0.f);
            As[ar][ak + i * 4 + 0] = wmma::__float_to_tf32(v.x);
            As[ar][ak + i * 4 + 1] = wmma::__float_to_tf32(v.y);
            As[ar][ak + i * 4 + 2] = wmma::__float_to_tf32(v.z);
            As[ar][ak + i * 4 + 3] = wmma::__float_to_tf32(v.w);
        }
        // load B tile (32 x 64) -> Bs[k][n], converted to tf32
        const float* bp = B + (long long)(k0 + br) * HC + n0 + bc;
#pragma unroll
        for (int i = 0; i < 2; i++) {
            float4 v = *(const float4*)(bp + i * 4);
            Bs[br][bc + i * 4 + 0] = wmma::__float_to_tf32(v.x);
            Bs[br][bc + i * 4 + 1] = wmma::__float_to_tf32(v.y);
            Bs[br][bc + i * 4 + 2] = wmma::__float_to_tf32(v.z);
            Bs[br][bc + i * 4 + 3] = wmma::__float_to_tf32(v.w);
        }
        __syncthreads();

#pragma unroll
        for (int kk = 0; kk < BK; kk += 8) {
            wmma::fragment<wmma::matrix_a, 16, 16, 8,
                           wmma::precision::tf32, wmma::row_major> a[2];
            wmma::fragment<wmma::matrix_b, 16, 16, 8,
                           wmma::precision::tf32, wmma::row_major> b[2];
#pragma unroll
            for (int i = 0; i < 2; i++)
                wmma::load_matrix_sync(a[i], &As[wm * 32 + i * 16][kk], BK + APAD);
#pragma unroll
            for (int j = 0; j < 2; j++)
                wmma::load_matrix_sync(b[j], &Bs[kk][wn * 32 + j * 16], BN + BPAD);
#pragma unroll
            for (int i = 0; i < 2; i++)
#pragma unroll
                for (int j = 0; j < 2; j++)
                    wmma::mma_sync(c[i][j], a[i], b[j], c[i][j]);
        }
        __syncthreads();
    }

    // epilogue: per-fragment row guard (M % 16 == 0 makes this exact)
#pragma unroll
    for (int i = 0; i < 2; i++) {
        int row0 = m0 + wm * 32 + i * 16;
        if (row0 >= M) continue;
#pragma unroll
        for (int j = 0; j < 2; j++) {
            int col0 = n0 + wn * 32 + j * 16;
            wmma::store_matrix_sync(&Cmat[(long long)row0 * HC + col0],
                                    c[i][j], HC, wmma::mem_row_major);
        }
    }
}

// ---------------- attention logits: a_src/a_dst per (node, head) -----------
__global__ void attn_kernel(const float* __restrict__ att_src,
                            const float* __restrict__ att_dst) {
    int gw = (blockIdx.x * blockDim.x + threadIdx.x) >> 5;
    int lane = threadIdx.x & 31;
    if (gw >= NN * NHEADS) return;
    int n = gw >> 2, hd = gw & 3;
    const float* hp = &g_h[(long long)n * HC + hd * CH];
    float h0 = hp[lane], h1 = hp[lane + 32];
    float s1 = h0 * att_src[hd * CH + lane] + h1 * att_src[hd * CH + lane + 32];
    float s2 = h0 * att_dst[hd * CH + lane] + h1 * att_dst[hd * CH + lane + 32];
#pragma unroll
    for (int d = 16; d; d >>= 1) {
        s1 += __shfl_xor_sync(0xffffffffu, s1, d);
        s2 += __shfl_xor_sync(0xffffffffu, s2, d);
    }
    if (lane == 0) {
        g_as[n * NHEADS + hd] = s1;
        g_ad[n * NHEADS + hd] = s2;
    }
}

// ---------------- aggregation: warp per destination node -------------------
__global__ void agg_kernel(const float* __restrict__ bias, float* __restrict__ out) {
    int warp = (blockIdx.x * blockDim.x + threadIdx.x) >> 5;
    int lane = threadIdx.x & 31;
    if (warp >= NN) return;
    int n = warp;
    int beg = g_rowptr[n], end = g_rowptr[n + 1];
    float4 ad4 = *(const float4*)&g_ad[n * 4];

    float m0 = -1e30f, m1 = -1e30f, m2 = -1e30f, m3 = -1e30f;
    for (int e = beg + lane; e < end; e += 32) {
        int s = g_col[e];
        float4 a4 = *(const float4*)&g_as[s * 4];
        float v;
        v = a4.x + ad4.x; v = v > 0.f ? v : SLOPE * v; m0 = fmaxf(m0, v);
        v = a4.y + ad4.y; v = v > 0.f ? v : SLOPE * v; m1 = fmaxf(m1, v);
        v = a4.z + ad4.z; v = v > 0.f ? v : SLOPE * v; m2 = fmaxf(m2, v);
        v = a4.w + ad4.w; v = v > 0.f ? v : SLOPE * v; m3 = fmaxf(m3, v);
    }
#pragma unroll
    for (int d = 16; d; d >>= 1) {
        m0 = fmaxf(m0, __shfl_xor_sync(0xffffffffu, m0, d));
        m1 = fmaxf(m1, __shfl_xor_sync(0xffffffffu, m1, d));
        m2 = fmaxf(m2, __shfl_xor_sync(0xffffffffu, m2, d));
        m3 = fmaxf(m3, __shfl_xor_sync(0xffffffffu, m3, d));
    }
    int hd = lane >> 3;
    float mh  = (hd == 0) ? m0 : (hd == 1) ? m1 : (hd == 2) ? m2 : m3;
    float adh = (hd == 0) ? ad4.x : (hd == 1) ? ad4.y : (hd == 2) ? ad4.z : ad4.w;

    int cbase = lane * 8;
    float acc[8] = {0.f, 0.f, 0.f, 0.f, 0.f, 0.f, 0.f, 0.f};
    float den = 0.f;
    for (int e = beg; e < end; e++) {
        int s = g_col[e];
        float av = g_as[s * 4 + hd];
        float ee = av + adh;
        ee = ee > 0.f ? ee : SLOPE * ee;
        float ex = __expf(ee - mh);
        den += ex;
        const float4* hp = (const float4*)&g_h[(long long)s * HC + cbase];
        float4 h0 = hp[0], h1 = hp[1];
        acc[0] += ex * h0.x; acc[1] += ex * h0.y; acc[2] += ex * h0.z; acc[3] += ex * h0.w;
        acc[4] += ex * h1.x; acc[5] += ex * h1.y; acc[6] += ex * h1.z; acc[7] += ex * h1.w;
    }
    float inv = 1.f / (den + 1e-16f);
    float4 b0 = *(const float4*)&bias[cbase];
    float4 b1 = *(const float4*)&bias[cbase + 4];
    float4 o0, o1;
    o0.x = fmaxf(acc[0] * inv + b0.x, 0.f);
    o0.y = fmaxf(acc[1] * inv + b0.y, 0.f);
    o0.z = fmaxf(acc[2] * inv + b0.z, 0.f);
    o0.w = fmaxf(acc[3] * inv + b0.w, 0.f);
    o1.x = fmaxf(acc[4] * inv + b1.x, 0.f);
    o1.y = fmaxf(acc[5] * inv + b1.y, 0.f);
    o1.z = fmaxf(acc[6] * inv + b1.z, 0.f);
    o1.w = fmaxf(acc[7] * inv + b1.w, 0.f);
    *(float4*)&out[(long long)n * HC + cbase]     = o0;
    *(float4*)&out[(long long)n * HC + cbase + 4] = o1;
}

// ---------------- launcher -------------------------------------------------
extern "C" void kernel_launch(void* const* d_in, const int* in_sizes, int n_in,
                              void* d_out, int out_size) {
    const float* x  = (const float*)d_in[0];
    const int*   ei = (const int*)d_in[1];
    int E = in_sizes[1] / 2;
    const int* src = ei;
    const int* dst = ei + E;

    const float* W[3]  = {(const float*)d_in[2], (const float*)d_in[6],  (const float*)d_in[10]};
    const float* AS[3] = {(const float*)d_in[3], (const float*)d_in[7],  (const float*)d_in[11]};
    const float* AD[3] = {(const float*)d_in[4], (const float*)d_in[8],  (const float*)d_in[12]};
    const float* BI[3] = {(const float*)d_in[5], (const float*)d_in[9],  (const float*)d_in[13]};
    float* out = (float*)d_out;

    float* gx = nullptr;
    float* gh = nullptr;
    cudaGetSymbolAddress((void**)&gx, g_x);
    cudaGetSymbolAddress((void**)&gh, g_h);

    // CSR build (edge_index is identical for all layers)
    zero_off_kernel<<<(NN + 255) / 256, 256>>>();
    count_kernel<<<(E + 255) / 256, 256>>>(dst, E);
    scan_kernel<<<1, 1024>>>();
    scatter_kernel<<<(E + 255) / 256, 256>>>(src, dst, E);

    dim3 ggrid(HC / BN, (NN + BM - 1) / BM);
    int attn_blocks = (NN * NHEADS * 32 + 255) / 256;
    int agg_blocks  = (NN + 7) / 8;

    // layer 0 (K = 128)
    gemm_tf32_kernel<<<ggrid, 256>>>(x, W[0], gh, NN, F0);
    attn_kernel<<<attn_blocks, 256>>>(AS[0], AD[0]);
    agg_kernel<<<agg_blocks, 256>>>(BI[0], gx);

    // layer 1 (K = 256)
    gemm_tf32_kernel<<<ggrid, 256>>>(gx, W[1], gh, NN, HC);
    attn_kernel<<<attn_blocks, 256>>>(AS[1], AD[1]);
    agg_kernel<<<agg_blocks, 256>>>(BI[1], gx);

    // layer 2 (K = 256), write final output
    gemm_tf32_kernel<<<ggrid, 256>>>(gx, W[2], gh, NN, HC);
    attn_kernel<<<attn_blocks, 256>>>(AS[2], AD[2]);
    agg_kernel<<<agg_blocks, 256>>>(BI[2], out);
}